// round 16
// baseline (speedup 1.0000x reference)
#include <cuda_runtime.h>
#include <cuda_fp16.h>
#include <cstdint>
#include <cstddef>

#define D_MODEL 512
#define NHEAD   8
#define DK      64
#define BATCH   2
#define SEQ     16384
#define MTOT    (BATCH*SEQ)      // 32768
#define NSPLIT  64
#define CHUNK   (SEQ/NSPLIT)     // 256

// ---------------- scratch ----------------
__device__ __half g_Qh[(size_t)MTOT * D_MODEL];     // Qf = softmax(Qproj)/8, fp16
__device__ __half g_Eh[(size_t)MTOT * D_MODEL];     // exp(K projection), fp16
__device__ __half g_Vh[(size_t)MTOT * D_MODEL];     // V projection, fp16
__device__ float  g_part[(size_t)BATCH*NHEAD*NSPLIT*DK*66];
__device__ __half g_Wh[(size_t)3 * D_MODEL * D_MODEL];
__device__ float  g_Wo32[(size_t)D_MODEL * D_MODEL];
__device__ __half g_Mh[(size_t)BATCH * D_MODEL * D_MODEL];

// ---------------- helpers ----------------
__device__ __forceinline__ uint32_t smem_to_u32(const void* p) {
    uint32_t a;
    asm("{ .reg .u64 t; cvta.to.shared.u64 t, %1; cvt.u32.u64 %0, t; }" : "=r"(a) : "l"(p));
    return a;
}

__device__ __forceinline__ void cp_async16(uint32_t saddr, const void* gptr) {
    uint64_t g;
    asm("cvta.to.global.u64 %0, %1;" : "=l"(g) : "l"(gptr));
    asm volatile("cp.async.ca.shared.global [%0], [%1], 16;" :: "r"(saddr), "l"(g) : "memory");
}
#define CP_COMMIT() asm volatile("cp.async.commit_group;" ::: "memory")
#define CP_WAIT1()  asm volatile("cp.async.wait_group 1;" ::: "memory")

__device__ __forceinline__ void ldmx4(uint32_t* r, uint32_t saddr) {
    asm volatile("ldmatrix.sync.aligned.m8n8.x4.shared.b16 {%0,%1,%2,%3}, [%4];"
        : "=r"(r[0]), "=r"(r[1]), "=r"(r[2]), "=r"(r[3]) : "r"(saddr));
}
__device__ __forceinline__ void ldmx4t(uint32_t* r, uint32_t saddr) {
    asm volatile("ldmatrix.sync.aligned.m8n8.x4.trans.shared.b16 {%0,%1,%2,%3}, [%4];"
        : "=r"(r[0]), "=r"(r[1]), "=r"(r[2]), "=r"(r[3]) : "r"(saddr));
}

__device__ __forceinline__ void mma_f16(float& c0, float& c1, float& c2, float& c3,
                                        uint32_t a0, uint32_t a1, uint32_t a2, uint32_t a3,
                                        uint32_t b0, uint32_t b1) {
    asm volatile(
        "mma.sync.aligned.m16n8k16.row.col.f32.f16.f16.f32 "
        "{%0,%1,%2,%3}, {%4,%5,%6,%7}, {%8,%9}, {%0,%1,%2,%3};\n"
        : "+f"(c0), "+f"(c1), "+f"(c2), "+f"(c3)
        : "r"(a0), "r"(a1), "r"(a2), "r"(a3), "r"(b0), "r"(b1));
}

// convert 8 fp32 -> 8 fp16, store as one 16B chunk
__device__ __forceinline__ void sts_h8(__half* p, float4 a, float4 b) {
    __half2 h[4];
    h[0] = __floats2half2_rn(a.x, a.y);
    h[1] = __floats2half2_rn(a.z, a.w);
    h[2] = __floats2half2_rn(b.x, b.y);
    h[3] = __floats2half2_rn(b.z, b.w);
    *(uint4*)p = *(uint4*)h;
}

// ================================================================================
// K0: transpose weights. z<3 -> fp16 g_Wh[z][n][k]; z==3 -> fp32 g_Wo32[n][k]
// ================================================================================
__global__ void __launch_bounds__(256)
transpose_w(const float* W0, const float* W1, const float* W2, const float* W3) {
    __shared__ float t[32][33];
    const int z = blockIdx.z;
    const float* W = (z == 0) ? W0 : (z == 1) ? W1 : (z == 2) ? W2 : W3;
    const int x0 = blockIdx.x * 32, y0 = blockIdx.y * 32;
    const int tx = threadIdx.x & 31, ty0 = threadIdx.x >> 5;
    #pragma unroll
    for (int i = 0; i < 4; i++) {
        int ty = ty0 + i * 8;
        t[ty][tx] = W[(size_t)(y0 + ty) * 512 + x0 + tx];
    }
    __syncthreads();
    if (z < 3) {
        __half* Wt = g_Wh + (size_t)z * D_MODEL * D_MODEL;
        #pragma unroll
        for (int i = 0; i < 4; i++) {
            int ty = ty0 + i * 8;
            Wt[(size_t)(x0 + ty) * 512 + y0 + tx] = __float2half_rn(t[tx][ty]);
        }
    } else {
        #pragma unroll
        for (int i = 0; i < 4; i++) {
            int ty = ty0 + i * 8;
            g_Wo32[(size_t)(x0 + ty) * 512 + y0 + tx] = t[tx][ty];
        }
    }
}

// ================================================================================
// GEMM fp16: C = A @ W^T + bias.  modes: 0=plain fp32, 1=exp fp16, 2=softmax fp16, 3=plain fp16
// tile 128x128, BK=64 (8 k-tiles), NST=3, 256 thr, warp 64x32.
// A32=true: A is fp32 in gmem, converted to fp16 during LDG->STS staging.
// ================================================================================
struct GemmArgs {
    const __half* A[3];       // fp16 A (A32=false)
    const float* Af[3];       // fp32 A (A32=true)
    const __half* W[3];
    const float* bias[3];
    float* C[3];
    __half* Ch[3];
    int mode[3];
    int batchW;
};

#define NST 3
#define ROWH 72
#define STG_H (128 * ROWH)
#define STG_B ((uint32_t)STG_H * 2)
#define GT_DSMEM (2 * NST * STG_H * 2)   // 110592 bytes

template<bool A32>
__global__ void __launch_bounds__(256, 2)
gemm_h(GemmArgs args) {
    extern __shared__ __half hsm[];
    const uint32_t sA = smem_to_u32(hsm);
    const uint32_t sB = sA + NST * STG_B;

    const int tid = threadIdx.x;
    const int warp = tid >> 5, lane = tid & 31;
    const int q = lane >> 2;
    const int z = blockIdx.z;
    const int m0 = blockIdx.x * 128, n0 = blockIdx.y * 128;
    const __half* W = args.W[z] + (args.batchW ? ((size_t)(m0 / SEQ) * D_MODEL * D_MODEL) : 0);
    const float* bias = args.bias[z];
    const int mode = args.mode[z];
    const int wm = (warp >> 2) * 64;
    const int wn = (warp & 3) * 32;

    float acc[4][4][4];
    #pragma unroll
    for (int i = 0; i < 4; i++)
        #pragma unroll
        for (int j = 0; j < 4; j++)
            #pragma unroll
            for (int kk = 0; kk < 4; kk++) acc[i][j][kk] = 0.f;

    const int srow = tid >> 3, sc8 = (tid & 7) * 8;
    const uint32_t sOffA = (uint32_t)(srow * ROWH + sc8) * 2;
    const uint32_t hOffA = (uint32_t)(srow * ROWH + sc8);
    const __half* gA  = A32 ? nullptr : &args.A[z][(size_t)(m0 + srow) * 512 + sc8];
    const float*  gAf = A32 ? &args.Af[z][(size_t)(m0 + srow) * 512 + sc8] : nullptr;
    const __half* gW = &W[(size_t)(n0 + srow) * 512 + sc8];

    const int lrow = lane & 15;
    const int lk = (lane >> 4) * 8;
    uint32_t aAd[4], bAd[2];
    #pragma unroll
    for (int mt = 0; mt < 4; mt++)
        aAd[mt] = sA + (uint32_t)((wm + mt * 16 + lrow) * ROWH + lk) * 2;
    #pragma unroll
    for (int nn = 0; nn < 2; nn++)
        bAd[nn] = sB + (uint32_t)((wn + nn * 16 + lrow) * ROWH + lk) * 2;

    // prologue: stages 0,1
    #pragma unroll
    for (int s = 0; s < NST - 1; s++) {
        if (A32) {
            #pragma unroll
            for (int i = 0; i < 4; i++) {
                float4 a0 = __ldg((const float4*)(gAf + (size_t)i * 32 * 512 + s * 64));
                float4 a1 = __ldg((const float4*)(gAf + (size_t)i * 32 * 512 + s * 64 + 4));
                sts_h8(hsm + s * STG_H + hOffA + (uint32_t)i * 32 * ROWH, a0, a1);
            }
        } else {
            #pragma unroll
            for (int i = 0; i < 4; i++)
                cp_async16(sA + s * STG_B + sOffA + (uint32_t)i * 32 * ROWH * 2, gA + (size_t)i * 32 * 512 + s * 64);
        }
        #pragma unroll
        for (int i = 0; i < 4; i++)
            cp_async16(sB + s * STG_B + sOffA + (uint32_t)i * 32 * ROWH * 2, gW + (size_t)i * 32 * 512 + s * 64);
        CP_COMMIT();
    }

    uint32_t stg = 0;
    #pragma unroll 1
    for (int kt = 0; kt < 8; kt++) {
        CP_WAIT1();
        __syncthreads();
        const bool do_stage = (kt + NST - 1 < 8);
        const uint32_t soB = ((kt + NST - 1) % NST) * STG_B;
        const uint32_t soH = ((kt + NST - 1) % NST) * STG_H;
        const int k0 = (kt + NST - 1) * 64;
        float4 ra0, ra1, rb0, rb1;
        if (do_stage) {
            #pragma unroll
            for (int i = 0; i < 4; i++)
                cp_async16(sB + soB + sOffA + (uint32_t)i * 32 * ROWH * 2, gW + (size_t)i * 32 * 512 + k0);
            if (A32) {
                ra0 = __ldg((const float4*)(gAf + k0));
                ra1 = __ldg((const float4*)(gAf + k0 + 4));
                rb0 = __ldg((const float4*)(gAf + (size_t)32 * 512 + k0));
                rb1 = __ldg((const float4*)(gAf + (size_t)32 * 512 + k0 + 4));
            } else {
                #pragma unroll
                for (int i = 0; i < 4; i++)
                    cp_async16(sA + soB + sOffA + (uint32_t)i * 32 * ROWH * 2, gA + (size_t)i * 32 * 512 + k0);
            }
        }
        CP_COMMIT();

        // compute ks=0,1
        #pragma unroll
        for (int ks = 0; ks < 2; ks++) {
            const uint32_t ko = stg + ks * 32;
            uint32_t af[4][4], bf[2][4];
            #pragma unroll
            for (int mt = 0; mt < 4; mt++) ldmx4(af[mt], aAd[mt] + ko);
            #pragma unroll
            for (int nn = 0; nn < 2; nn++) ldmx4(bf[nn], bAd[nn] + ko);
            #pragma unroll
            for (int mt = 0; mt < 4; mt++)
                #pragma unroll
                for (int nt = 0; nt < 4; nt++) {
                    int nn = nt >> 1, o = nt & 1;
                    mma_f16(acc[mt][nt][0], acc[mt][nt][1], acc[mt][nt][2], acc[mt][nt][3],
                            af[mt][0], af[mt][1], af[mt][2], af[mt][3],
                            bf[nn][o], bf[nn][o + 2]);
                }
        }

        if (A32 && do_stage) {
            sts_h8(hsm + soH + hOffA,                       ra0, ra1);
            sts_h8(hsm + soH + hOffA + (uint32_t)32 * ROWH, rb0, rb1);
            ra0 = __ldg((const float4*)(gAf + (size_t)64 * 512 + k0));
            ra1 = __ldg((const float4*)(gAf + (size_t)64 * 512 + k0 + 4));
            rb0 = __ldg((const float4*)(gAf + (size_t)96 * 512 + k0));
            rb1 = __ldg((const float4*)(gAf + (size_t)96 * 512 + k0 + 4));
        }

        // compute ks=2,3
        #pragma unroll
        for (int ks = 2; ks < 4; ks++) {
            const uint32_t ko = stg + ks * 32;
            uint32_t af[4][4], bf[2][4];
            #pragma unroll
            for (int mt = 0; mt < 4; mt++) ldmx4(af[mt], aAd[mt] + ko);
            #pragma unroll
            for (int nn = 0; nn < 2; nn++) ldmx4(bf[nn], bAd[nn] + ko);
            #pragma unroll
            for (int mt = 0; mt < 4; mt++)
                #pragma unroll
                for (int nt = 0; nt < 4; nt++) {
                    int nn = nt >> 1, o = nt & 1;
                    mma_f16(acc[mt][nt][0], acc[mt][nt][1], acc[mt][nt][2], acc[mt][nt][3],
                            af[mt][0], af[mt][1], af[mt][2], af[mt][3],
                            bf[nn][o], bf[nn][o + 2]);
                }
        }

        if (A32 && do_stage) {
            sts_h8(hsm + soH + hOffA + (uint32_t)64 * ROWH, ra0, ra1);
            sts_h8(hsm + soH + hOffA + (uint32_t)96 * ROWH, rb0, rb1);
        }

        stg += STG_B;
        if (stg == NST * STG_B) stg = 0;
    }

    // ---- epilogue ----
    if (mode == 2) {
        __half* Ch = args.Ch[z];
        float* rowsum = (float*)hsm;
        __syncthreads();
        float rs[4][2];
        #pragma unroll
        for (int mt = 0; mt < 4; mt++) { rs[mt][0] = 0.f; rs[mt][1] = 0.f; }
        #pragma unroll
        for (int mt = 0; mt < 4; mt++)
            #pragma unroll
            for (int nt = 0; nt < 4; nt++) {
                int n = n0 + wn + nt * 8 + (lane & 3) * 2;
                float b0 = __ldg(&bias[n]), b1 = __ldg(&bias[n + 1]);
                float e0 = __expf(acc[mt][nt][0] + b0);
                float e1 = __expf(acc[mt][nt][1] + b1);
                float e2 = __expf(acc[mt][nt][2] + b0);
                float e3 = __expf(acc[mt][nt][3] + b1);
                acc[mt][nt][0] = e0; acc[mt][nt][1] = e1;
                acc[mt][nt][2] = e2; acc[mt][nt][3] = e3;
                rs[mt][0] += e0 + e1;
                rs[mt][1] += e2 + e3;
            }
        #pragma unroll
        for (int mt = 0; mt < 4; mt++)
            #pragma unroll
            for (int hf = 0; hf < 2; hf++) {
                float rr = rs[mt][hf];
                rr += __shfl_xor_sync(0xffffffffu, rr, 1);
                rr += __shfl_xor_sync(0xffffffffu, rr, 2);
                if ((lane & 3) == 0)
                    rowsum[(warp & 3) * 128 + wm + mt * 16 + q + hf * 8] = rr;
            }
        __syncthreads();
        #pragma unroll
        for (int mt = 0; mt < 4; mt++) {
            #pragma unroll
            for (int hf = 0; hf < 2; hf++) {
                int row = wm + mt * 16 + q + hf * 8;
                float tot = rowsum[(warp & 3) * 128 + row] + rowsum[((warp & 3) ^ 1) * 128 + row];
                float sc = 0.125f / tot;
                int m = m0 + row;
                #pragma unroll
                for (int nt = 0; nt < 4; nt++) {
                    int n = n0 + wn + nt * 8 + (lane & 3) * 2;
                    __half2 hv = __floats2half2_rn(acc[mt][nt][hf * 2 + 0] * sc,
                                                   acc[mt][nt][hf * 2 + 1] * sc);
                    *(__half2*)&Ch[(size_t)m * 512 + n] = hv;
                }
            }
        }
    } else if (mode == 0) {
        float* C = args.C[z];
        #pragma unroll
        for (int mt = 0; mt < 4; mt++)
            #pragma unroll
            for (int nt = 0; nt < 4; nt++) {
                int m = m0 + wm + mt * 16 + q;
                int n = n0 + wn + nt * 8 + (lane & 3) * 2;
                float b0 = __ldg(&bias[n]), b1 = __ldg(&bias[n + 1]);
                *(float2*)&C[(size_t)m * 512 + n]       = make_float2(acc[mt][nt][0] + b0, acc[mt][nt][1] + b1);
                *(float2*)&C[(size_t)(m + 8) * 512 + n] = make_float2(acc[mt][nt][2] + b0, acc[mt][nt][3] + b1);
            }
    } else {
        __half* Ch = args.Ch[z];
        const bool do_exp = (mode == 1);
        #pragma unroll
        for (int mt = 0; mt < 4; mt++)
            #pragma unroll
            for (int nt = 0; nt < 4; nt++) {
                int m = m0 + wm + mt * 16 + q;
                int n = n0 + wn + nt * 8 + (lane & 3) * 2;
                float b0 = __ldg(&bias[n]), b1 = __ldg(&bias[n + 1]);
                float v0 = acc[mt][nt][0] + b0;
                float v1 = acc[mt][nt][1] + b1;
                float v2 = acc[mt][nt][2] + b0;
                float v3 = acc[mt][nt][3] + b1;
                if (do_exp) { v0 = __expf(v0); v1 = __expf(v1); v2 = __expf(v2); v3 = __expf(v3); }
                *(__half2*)&Ch[(size_t)m * 512 + n]       = __floats2half2_rn(v0, v1);
                *(__half2*)&Ch[(size_t)(m + 8) * 512 + n] = __floats2half2_rn(v2, v3);
            }
    }
}

// ================================================================================
// K2: per-(b,h,split) context partials via fp16 mma + ldmatrix.trans.
// Two-stage double-buffer (37 KB smem).  [R11 config]
// ================================================================================
#define CPT_H (64 * 72)
#define CPT_B ((uint32_t)CPT_H * 2)
#define CP_DSMEM (4 * CPT_H * 2 + 256)

__global__ void __launch_bounds__(128)
ctx_partial_kernel() {
    extern __shared__ __half smh[];
    const int sp = blockIdx.x, h = blockIdx.y, b = blockIdx.z;
    const int tid = threadIdx.x, warp = tid >> 5, lane = tid & 31;
    const int q = lane >> 2, r = lane & 3;
    const int rowbase = b * SEQ + sp * CHUNK;
    const int coloff = h * 64;
    const uint32_t sbase = smem_to_u32(smh);

    float acc[32];
    #pragma unroll
    for (int i = 0; i < 32; i++) acc[i] = 0.f;
    float ssum = 0.f;
    const int sd = tid & 63;
    const int sr0 = (tid >> 6) * 32;

    const int srow = tid >> 3;
    const int sc8  = (tid & 7) * 8;
    const uint32_t sOff = (uint32_t)(srow * 72 + sc8) * 2;

    const int lg = lane >> 3;
    const int lrowA = (lg >> 1) * 8 + (lane & 7);
    const int lcolA = warp * 16 + (lg & 1) * 8;
    const int lrowB = (lg & 1) * 8 + (lane & 7);
    const int lcolB0 = (lg >> 1) * 8;

    #pragma unroll
    for (int i = 0; i < 4; i++) {
        int row = srow + i * 16;
        uint32_t so = sOff + (uint32_t)i * 16 * 72 * 2;
        cp_async16(sbase + so,         &g_Eh[(size_t)(rowbase + row) * 512 + coloff + sc8]);
        cp_async16(sbase + CPT_B + so, &g_Vh[(size_t)(rowbase + row) * 512 + coloff + sc8]);
    }
    CP_COMMIT();

    #pragma unroll 1
    for (int g = 0; g < 4; g++) {
        __syncthreads();
        if (g + 1 < 4) {
            uint32_t bb = sbase + (uint32_t)((g + 1) & 1) * 2 * CPT_B;
            const int gr = rowbase + (g + 1) * 64;
            #pragma unroll
            for (int i = 0; i < 4; i++) {
                int row = srow + i * 16;
                uint32_t so = sOff + (uint32_t)i * 16 * 72 * 2;
                cp_async16(bb + so,         &g_Eh[(size_t)(gr + row) * 512 + coloff + sc8]);
                cp_async16(bb + CPT_B + so, &g_Vh[(size_t)(gr + row) * 512 + coloff + sc8]);
            }
        }
        CP_COMMIT();
        CP_WAIT1();
        __syncthreads();

        const uint32_t Eb = sbase + (uint32_t)(g & 1) * 2 * CPT_B;
        const uint32_t Vb = Eb + CPT_B;
        const __half* Es = (const __half*)(smh + (size_t)(g & 1) * 2 * CPT_H);

        #pragma unroll 8
        for (int n = 0; n < 32; n++) ssum += __half2float(Es[(sr0 + n) * 72 + sd]);

        #pragma unroll
        for (int kb = 0; kb < 4; kb++) {
            uint32_t af[4], bf[4][4];
            ldmx4t(af, Eb + (uint32_t)((kb * 16 + lrowA) * 72 + lcolA) * 2);
            #pragma unroll
            for (int eb = 0; eb < 4; eb++)
                ldmx4t(bf[eb], Vb + (uint32_t)((kb * 16 + lrowB) * 72 + eb * 16 + lcolB0) * 2);
            #pragma unroll
            for (int nt = 0; nt < 8; nt++) {
                int eb = nt >> 1, o = (nt & 1) * 2;
                mma_f16(acc[nt * 4 + 0], acc[nt * 4 + 1], acc[nt * 4 + 2], acc[nt * 4 + 3],
                        af[0], af[1], af[2], af[3],
                        bf[eb][o], bf[eb][o + 1]);
            }
        }
    }

    float* P = g_part + ((size_t)((b * NHEAD + h) * NSPLIT + sp)) * DK * 66;
    #pragma unroll
    for (int nt = 0; nt < 8; nt++) {
        int e = nt * 8 + r * 2;
        *(float2*)&P[(warp * 16 + q) * 66 + e]     = make_float2(acc[nt * 4 + 0], acc[nt * 4 + 1]);
        *(float2*)&P[(warp * 16 + q + 8) * 66 + e] = make_float2(acc[nt * 4 + 2], acc[nt * 4 + 3]);
    }
    float* ssc = (float*)(smh + 4 * CPT_H);
    if (tid >= 64) ssc[tid - 64] = ssum;
    __syncthreads();
    if (tid < 64) P[tid * 66 + 64] = ssum + ssc[tid];
}

// ================================================================================
// K3: FUSED reduce + normalize + ctx@Wo -> g_Mh.  grid (16 bh, 4 d-slabs), 256 thr.
// Block (bh, y): owns d rows [16y, 16y+16). Phase 1: reduce its 16x66 partial rows
// over 64 splits. Phase 2: normalize in place. Phase 3: M_b[nf][h*64+d] for all nf.
// ================================================================================
__global__ void __launch_bounds__(256)
ctx_rm_kernel() {
    const int bh = blockIdx.x, y = blockIdx.y;
    const int b = bh >> 3, h = bh & 7;
    const int tid = threadIdx.x;
    __shared__ float s[16 * 66];    // 1056

    const float* P = g_part + (size_t)bh * NSPLIT * 4224 + y * 16 * 66;
    for (int idx = tid; idx < 1056; idx += 256) {
        float a0 = 0.f, a1 = 0.f, a2 = 0.f, a3 = 0.f;
        for (int sp = 0; sp < 64; sp += 4) {
            a0 += P[(size_t)(sp + 0) * 4224 + idx];
            a1 += P[(size_t)(sp + 1) * 4224 + idx];
            a2 += P[(size_t)(sp + 2) * 4224 + idx];
            a3 += P[(size_t)(sp + 3) * 4224 + idx];
        }
        s[idx] = (a0 + a1) + (a2 + a3);
    }
    __syncthreads();
    // normalize rows (e entries only; denominator at col 64 untouched)
    for (int i = tid; i < 16 * 64; i += 256) {
        int dl = i >> 6, e = i & 63;
        s[dl * 66 + e] = s[dl * 66 + e] / s[dl * 66 + 64];
    }
    __syncthreads();

    // ctx_mm for this d-slab: thread (dl = tid>>4, ng = tid&15) covers nf [ng*32, ng*32+32)
    const int dl = tid >> 4;
    const int ng = tid & 15;
    const int d  = y * 16 + dl;
    const int kc = h * 64 + d;
    __half* Mb = g_Mh + (size_t)b * D_MODEL * D_MODEL;

    for (int nfb = ng * 32; nfb < ng * 32 + 32; nfb += 8) {
        float a8[8];
        #pragma unroll
        for (int i = 0; i < 8; i++) a8[i] = 0.f;
        #pragma unroll 4
        for (int e0 = 0; e0 < 64; e0 += 4) {
            float c0 = s[dl * 66 + e0 + 0];
            float c1 = s[dl * 66 + e0 + 1];
            float c2 = s[dl * 66 + e0 + 2];
            float c3 = s[dl * 66 + e0 + 3];
            #pragma unroll
            for (int i = 0; i < 8; i++) {
                float4 w = *(const float4*)&g_Wo32[(size_t)(nfb + i) * 512 + h * 64 + e0];
                a8[i] += w.x * c0 + w.y * c1 + w.z * c2 + w.w * c3;
            }
        }
        #pragma unroll
        for (int i = 0; i < 8; i++)
            Mb[(size_t)(nfb + i) * 512 + kc] = __float2half_rn(a8[i]);
    }
}

// ================================================================================
// launch
// ================================================================================
extern "C" void kernel_launch(void* const* d_in, const int* in_sizes, int n_in,
                              void* d_out, int out_size) {
    const float* q  = (const float*)d_in[0];
    const float* k  = (const float*)d_in[1];
    const float* v  = (const float*)d_in[2];
    const float* Wq = (const float*)d_in[3];
    const float* bq = (const float*)d_in[4];
    const float* Wk = (const float*)d_in[5];
    const float* bk = (const float*)d_in[6];
    const float* Wv = (const float*)d_in[7];
    const float* bv = (const float*)d_in[8];
    const float* Wo = (const float*)d_in[9];
    const float* bo = (const float*)d_in[10];

    __half *pQh, *pEh, *pVh, *pWh, *pMh;
    cudaGetSymbolAddress((void**)&pQh, g_Qh);
    cudaGetSymbolAddress((void**)&pEh, g_Eh);
    cudaGetSymbolAddress((void**)&pVh, g_Vh);
    cudaGetSymbolAddress((void**)&pWh, g_Wh);
    cudaGetSymbolAddress((void**)&pMh, g_Mh);

    cudaFuncSetAttribute(gemm_h<true>,  cudaFuncAttributeMaxDynamicSharedMemorySize, GT_DSMEM);
    cudaFuncSetAttribute(gemm_h<false>, cudaFuncAttributeMaxDynamicSharedMemorySize, GT_DSMEM);
    cudaFuncSetAttribute(ctx_partial_kernel, cudaFuncAttributeMaxDynamicSharedMemorySize, CP_DSMEM);

    transpose_w<<<dim3(16, 16, 4), 256>>>(Wq, Wk, Wv, Wo);            // #1

    // projections (fp32 A fused conversion): z0=Q(softmax fp16), z1=K(exp fp16), z2=V(plain fp16)
    GemmArgs pa;
    pa.A[0] = nullptr; pa.A[1] = nullptr; pa.A[2] = nullptr;
    pa.Af[0] = q; pa.Af[1] = k; pa.Af[2] = v;
    pa.W[0] = pWh + (size_t)0 * 262144; pa.W[1] = pWh + (size_t)1 * 262144; pa.W[2] = pWh + (size_t)2 * 262144;
    pa.bias[0] = bq; pa.bias[1] = bk; pa.bias[2] = bv;
    pa.C[0] = nullptr; pa.C[1] = nullptr; pa.C[2] = nullptr;
    pa.Ch[0] = pQh; pa.Ch[1] = pEh; pa.Ch[2] = pVh;
    pa.mode[0] = 2; pa.mode[1] = 1; pa.mode[2] = 3;
    pa.batchW = 0;
    gemm_h<true><<<dim3(MTOT / 128, 4, 3), 256, GT_DSMEM>>>(pa);      // #2

    ctx_partial_kernel<<<dim3(NSPLIT, NHEAD, BATCH), 128, CP_DSMEM>>>();   // #3
    ctx_rm_kernel<<<dim3(BATCH * NHEAD, 4), 256>>>();                 // #4 -> ncu

    // output: out = Qf @ M_b + bo (fp16 A path, fp32 out)
    GemmArgs oa;
    oa.A[0] = pQh; oa.A[1] = pQh; oa.A[2] = pQh;
    oa.Af[0] = nullptr; oa.Af[1] = nullptr; oa.Af[2] = nullptr;
    oa.W[0] = pMh; oa.W[1] = pMh; oa.W[2] = pMh;
    oa.bias[0] = bo; oa.bias[1] = bo; oa.bias[2] = bo;
    oa.C[0] = (float*)d_out; oa.C[1] = oa.C[0]; oa.C[2] = oa.C[0];
    oa.Ch[0] = nullptr; oa.Ch[1] = nullptr; oa.Ch[2] = nullptr;
    oa.mode[0] = 0; oa.mode[1] = 0; oa.mode[2] = 0;
    oa.batchW = 1;
    gemm_h<false><<<dim3(MTOT / 128, 4, 1), 256, GT_DSMEM>>>(oa);     // #5
}

// round 17
// speedup vs baseline: 1.1056x; 1.1056x over previous
#include <cuda_runtime.h>
#include <cuda_fp16.h>
#include <cstdint>
#include <cstddef>

#define D_MODEL 512
#define NHEAD   8
#define DK      64
#define BATCH   2
#define SEQ     16384
#define MTOT    (BATCH*SEQ)      // 32768
#define NSPLIT  64
#define CHUNK   (SEQ/NSPLIT)     // 256

// ---------------- scratch ----------------
__device__ __half g_Qh[(size_t)MTOT * D_MODEL];     // Qf = softmax(Qproj)/8, fp16
__device__ __half g_Eh[(size_t)MTOT * D_MODEL];     // exp(K projection), fp16
__device__ __half g_Vh[(size_t)MTOT * D_MODEL];     // V projection, fp16
__device__ float  g_part[(size_t)BATCH*NHEAD*NSPLIT*DK*66];
__device__ float  g_ctx [(size_t)BATCH*NHEAD*DK*DK];
__device__ __half g_Wh[(size_t)3 * D_MODEL * D_MODEL];
__device__ float  g_Wo32[(size_t)D_MODEL * D_MODEL];
__device__ __half g_Mh[(size_t)BATCH * D_MODEL * D_MODEL];

// ---------------- helpers ----------------
__device__ __forceinline__ uint32_t smem_to_u32(const void* p) {
    uint32_t a;
    asm("{ .reg .u64 t; cvta.to.shared.u64 t, %1; cvt.u32.u64 %0, t; }" : "=r"(a) : "l"(p));
    return a;
}

__device__ __forceinline__ void cp_async16(uint32_t saddr, const void* gptr) {
    uint64_t g;
    asm("cvta.to.global.u64 %0, %1;" : "=l"(g) : "l"(gptr));
    asm volatile("cp.async.ca.shared.global [%0], [%1], 16;" :: "r"(saddr), "l"(g) : "memory");
}
#define CP_COMMIT() asm volatile("cp.async.commit_group;" ::: "memory")
#define CP_WAIT1()  asm volatile("cp.async.wait_group 1;" ::: "memory")

__device__ __forceinline__ void ldmx4(uint32_t* r, uint32_t saddr) {
    asm volatile("ldmatrix.sync.aligned.m8n8.x4.shared.b16 {%0,%1,%2,%3}, [%4];"
        : "=r"(r[0]), "=r"(r[1]), "=r"(r[2]), "=r"(r[3]) : "r"(saddr));
}
__device__ __forceinline__ void ldmx4t(uint32_t* r, uint32_t saddr) {
    asm volatile("ldmatrix.sync.aligned.m8n8.x4.trans.shared.b16 {%0,%1,%2,%3}, [%4];"
        : "=r"(r[0]), "=r"(r[1]), "=r"(r[2]), "=r"(r[3]) : "r"(saddr));
}

__device__ __forceinline__ void mma_f16(float& c0, float& c1, float& c2, float& c3,
                                        uint32_t a0, uint32_t a1, uint32_t a2, uint32_t a3,
                                        uint32_t b0, uint32_t b1) {
    asm volatile(
        "mma.sync.aligned.m16n8k16.row.col.f32.f16.f16.f32 "
        "{%0,%1,%2,%3}, {%4,%5,%6,%7}, {%8,%9}, {%0,%1,%2,%3};\n"
        : "+f"(c0), "+f"(c1), "+f"(c2), "+f"(c3)
        : "r"(a0), "r"(a1), "r"(a2), "r"(a3), "r"(b0), "r"(b1));
}

// convert 8 fp32 -> 8 fp16, store as one 16B chunk
__device__ __forceinline__ void sts_h8(__half* p, float4 a, float4 b) {
    __half2 h[4];
    h[0] = __floats2half2_rn(a.x, a.y);
    h[1] = __floats2half2_rn(a.z, a.w);
    h[2] = __floats2half2_rn(b.x, b.y);
    h[3] = __floats2half2_rn(b.z, b.w);
    *(uint4*)p = *(uint4*)h;
}

__global__ void noop_kernel() {}

// ================================================================================
// K0: transpose weights. z<3 -> fp16 g_Wh[z][n][k]; z==3 -> fp32 g_Wo32[n][k]
// ================================================================================
__global__ void __launch_bounds__(256)
transpose_w(const float* W0, const float* W1, const float* W2, const float* W3) {
    __shared__ float t[32][33];
    const int z = blockIdx.z;
    const float* W = (z == 0) ? W0 : (z == 1) ? W1 : (z == 2) ? W2 : W3;
    const int x0 = blockIdx.x * 32, y0 = blockIdx.y * 32;
    const int tx = threadIdx.x & 31, ty0 = threadIdx.x >> 5;
    #pragma unroll
    for (int i = 0; i < 4; i++) {
        int ty = ty0 + i * 8;
        t[ty][tx] = W[(size_t)(y0 + ty) * 512 + x0 + tx];
    }
    __syncthreads();
    if (z < 3) {
        __half* Wt = g_Wh + (size_t)z * D_MODEL * D_MODEL;
        #pragma unroll
        for (int i = 0; i < 4; i++) {
            int ty = ty0 + i * 8;
            Wt[(size_t)(x0 + ty) * 512 + y0 + tx] = __float2half_rn(t[tx][ty]);
        }
    } else {
        #pragma unroll
        for (int i = 0; i < 4; i++) {
            int ty = ty0 + i * 8;
            g_Wo32[(size_t)(x0 + ty) * 512 + y0 + tx] = t[tx][ty];
        }
    }
}

// ================================================================================
// GEMM fp16: C = A @ W^T + bias.  modes: 0=plain fp32, 1=exp fp16, 2=softmax fp16, 3=plain fp16
// tile 128x128, BK=64 (8 k-tiles), NST=3, 256 thr, warp 64x32.
// A32=true: A is fp32 in gmem, converted to fp16 during LDG->STS staging.
// ================================================================================
struct GemmArgs {
    const __half* A[3];       // fp16 A (A32=false)
    const float* Af[3];       // fp32 A (A32=true)
    const __half* W[3];
    const float* bias[3];
    float* C[3];
    __half* Ch[3];
    int mode[3];
    int batchW;
};

#define NST 3
#define ROWH 72
#define STG_H (128 * ROWH)
#define STG_B ((uint32_t)STG_H * 2)
#define GT_DSMEM (2 * NST * STG_H * 2)   // 110592 bytes

template<bool A32>
__global__ void __launch_bounds__(256, 2)
gemm_h(GemmArgs args) {
    extern __shared__ __half hsm[];
    const uint32_t sA = smem_to_u32(hsm);
    const uint32_t sB = sA + NST * STG_B;

    const int tid = threadIdx.x;
    const int warp = tid >> 5, lane = tid & 31;
    const int q = lane >> 2;
    const int z = blockIdx.z;
    const int m0 = blockIdx.x * 128, n0 = blockIdx.y * 128;
    const __half* W = args.W[z] + (args.batchW ? ((size_t)(m0 / SEQ) * D_MODEL * D_MODEL) : 0);
    const float* bias = args.bias[z];
    const int mode = args.mode[z];
    const int wm = (warp >> 2) * 64;
    const int wn = (warp & 3) * 32;

    float acc[4][4][4];
    #pragma unroll
    for (int i = 0; i < 4; i++)
        #pragma unroll
        for (int j = 0; j < 4; j++)
            #pragma unroll
            for (int kk = 0; kk < 4; kk++) acc[i][j][kk] = 0.f;

    const int srow = tid >> 3, sc8 = (tid & 7) * 8;
    const uint32_t sOffA = (uint32_t)(srow * ROWH + sc8) * 2;
    const uint32_t hOffA = (uint32_t)(srow * ROWH + sc8);
    const __half* gA  = A32 ? nullptr : &args.A[z][(size_t)(m0 + srow) * 512 + sc8];
    const float*  gAf = A32 ? &args.Af[z][(size_t)(m0 + srow) * 512 + sc8] : nullptr;
    const __half* gW = &W[(size_t)(n0 + srow) * 512 + sc8];

    const int lrow = lane & 15;
    const int lk = (lane >> 4) * 8;
    uint32_t aAd[4], bAd[2];
    #pragma unroll
    for (int mt = 0; mt < 4; mt++)
        aAd[mt] = sA + (uint32_t)((wm + mt * 16 + lrow) * ROWH + lk) * 2;
    #pragma unroll
    for (int nn = 0; nn < 2; nn++)
        bAd[nn] = sB + (uint32_t)((wn + nn * 16 + lrow) * ROWH + lk) * 2;

    // prologue: stages 0,1
    #pragma unroll
    for (int s = 0; s < NST - 1; s++) {
        if (A32) {
            #pragma unroll
            for (int i = 0; i < 4; i++) {
                float4 a0 = __ldg((const float4*)(gAf + (size_t)i * 32 * 512 + s * 64));
                float4 a1 = __ldg((const float4*)(gAf + (size_t)i * 32 * 512 + s * 64 + 4));
                sts_h8(hsm + s * STG_H + hOffA + (uint32_t)i * 32 * ROWH, a0, a1);
            }
        } else {
            #pragma unroll
            for (int i = 0; i < 4; i++)
                cp_async16(sA + s * STG_B + sOffA + (uint32_t)i * 32 * ROWH * 2, gA + (size_t)i * 32 * 512 + s * 64);
        }
        #pragma unroll
        for (int i = 0; i < 4; i++)
            cp_async16(sB + s * STG_B + sOffA + (uint32_t)i * 32 * ROWH * 2, gW + (size_t)i * 32 * 512 + s * 64);
        CP_COMMIT();
    }

    uint32_t stg = 0;
    #pragma unroll 1
    for (int kt = 0; kt < 8; kt++) {
        CP_WAIT1();
        __syncthreads();
        const bool do_stage = (kt + NST - 1 < 8);
        const uint32_t soB = ((kt + NST - 1) % NST) * STG_B;
        const uint32_t soH = ((kt + NST - 1) % NST) * STG_H;
        const int k0 = (kt + NST - 1) * 64;
        float4 ra0, ra1, rb0, rb1;
        if (do_stage) {
            #pragma unroll
            for (int i = 0; i < 4; i++)
                cp_async16(sB + soB + sOffA + (uint32_t)i * 32 * ROWH * 2, gW + (size_t)i * 32 * 512 + k0);
            if (A32) {
                ra0 = __ldg((const float4*)(gAf + k0));
                ra1 = __ldg((const float4*)(gAf + k0 + 4));
                rb0 = __ldg((const float4*)(gAf + (size_t)32 * 512 + k0));
                rb1 = __ldg((const float4*)(gAf + (size_t)32 * 512 + k0 + 4));
            } else {
                #pragma unroll
                for (int i = 0; i < 4; i++)
                    cp_async16(sA + soB + sOffA + (uint32_t)i * 32 * ROWH * 2, gA + (size_t)i * 32 * 512 + k0);
            }
        }
        CP_COMMIT();

        // compute ks=0,1
        #pragma unroll
        for (int ks = 0; ks < 2; ks++) {
            const uint32_t ko = stg + ks * 32;
            uint32_t af[4][4], bf[2][4];
            #pragma unroll
            for (int mt = 0; mt < 4; mt++) ldmx4(af[mt], aAd[mt] + ko);
            #pragma unroll
            for (int nn = 0; nn < 2; nn++) ldmx4(bf[nn], bAd[nn] + ko);
            #pragma unroll
            for (int mt = 0; mt < 4; mt++)
                #pragma unroll
                for (int nt = 0; nt < 4; nt++) {
                    int nn = nt >> 1, o = nt & 1;
                    mma_f16(acc[mt][nt][0], acc[mt][nt][1], acc[mt][nt][2], acc[mt][nt][3],
                            af[mt][0], af[mt][1], af[mt][2], af[mt][3],
                            bf[nn][o], bf[nn][o + 2]);
                }
        }

        if (A32 && do_stage) {
            sts_h8(hsm + soH + hOffA,                       ra0, ra1);
            sts_h8(hsm + soH + hOffA + (uint32_t)32 * ROWH, rb0, rb1);
            ra0 = __ldg((const float4*)(gAf + (size_t)64 * 512 + k0));
            ra1 = __ldg((const float4*)(gAf + (size_t)64 * 512 + k0 + 4));
            rb0 = __ldg((const float4*)(gAf + (size_t)96 * 512 + k0));
            rb1 = __ldg((const float4*)(gAf + (size_t)96 * 512 + k0 + 4));
        }

        // compute ks=2,3
        #pragma unroll
        for (int ks = 2; ks < 4; ks++) {
            const uint32_t ko = stg + ks * 32;
            uint32_t af[4][4], bf[2][4];
            #pragma unroll
            for (int mt = 0; mt < 4; mt++) ldmx4(af[mt], aAd[mt] + ko);
            #pragma unroll
            for (int nn = 0; nn < 2; nn++) ldmx4(bf[nn], bAd[nn] + ko);
            #pragma unroll
            for (int mt = 0; mt < 4; mt++)
                #pragma unroll
                for (int nt = 0; nt < 4; nt++) {
                    int nn = nt >> 1, o = nt & 1;
                    mma_f16(acc[mt][nt][0], acc[mt][nt][1], acc[mt][nt][2], acc[mt][nt][3],
                            af[mt][0], af[mt][1], af[mt][2], af[mt][3],
                            bf[nn][o], bf[nn][o + 2]);
                }
        }

        if (A32 && do_stage) {
            sts_h8(hsm + soH + hOffA + (uint32_t)64 * ROWH, ra0, ra1);
            sts_h8(hsm + soH + hOffA + (uint32_t)96 * ROWH, rb0, rb1);
        }

        stg += STG_B;
        if (stg == NST * STG_B) stg = 0;
    }

    // ---- epilogue ----
    if (mode == 2) {
        __half* Ch = args.Ch[z];
        float* rowsum = (float*)hsm;
        __syncthreads();
        float rs[4][2];
        #pragma unroll
        for (int mt = 0; mt < 4; mt++) { rs[mt][0] = 0.f; rs[mt][1] = 0.f; }
        #pragma unroll
        for (int mt = 0; mt < 4; mt++)
            #pragma unroll
            for (int nt = 0; nt < 4; nt++) {
                int n = n0 + wn + nt * 8 + (lane & 3) * 2;
                float b0 = __ldg(&bias[n]), b1 = __ldg(&bias[n + 1]);
                float e0 = __expf(acc[mt][nt][0] + b0);
                float e1 = __expf(acc[mt][nt][1] + b1);
                float e2 = __expf(acc[mt][nt][2] + b0);
                float e3 = __expf(acc[mt][nt][3] + b1);
                acc[mt][nt][0] = e0; acc[mt][nt][1] = e1;
                acc[mt][nt][2] = e2; acc[mt][nt][3] = e3;
                rs[mt][0] += e0 + e1;
                rs[mt][1] += e2 + e3;
            }
        #pragma unroll
        for (int mt = 0; mt < 4; mt++)
            #pragma unroll
            for (int hf = 0; hf < 2; hf++) {
                float rr = rs[mt][hf];
                rr += __shfl_xor_sync(0xffffffffu, rr, 1);
                rr += __shfl_xor_sync(0xffffffffu, rr, 2);
                if ((lane & 3) == 0)
                    rowsum[(warp & 3) * 128 + wm + mt * 16 + q + hf * 8] = rr;
            }
        __syncthreads();
        #pragma unroll
        for (int mt = 0; mt < 4; mt++) {
            #pragma unroll
            for (int hf = 0; hf < 2; hf++) {
                int row = wm + mt * 16 + q + hf * 8;
                float tot = rowsum[(warp & 3) * 128 + row] + rowsum[((warp & 3) ^ 1) * 128 + row];
                float sc = 0.125f / tot;
                int m = m0 + row;
                #pragma unroll
                for (int nt = 0; nt < 4; nt++) {
                    int n = n0 + wn + nt * 8 + (lane & 3) * 2;
                    __half2 hv = __floats2half2_rn(acc[mt][nt][hf * 2 + 0] * sc,
                                                   acc[mt][nt][hf * 2 + 1] * sc);
                    *(__half2*)&Ch[(size_t)m * 512 + n] = hv;
                }
            }
        }
    } else if (mode == 0) {
        float* C = args.C[z];
        #pragma unroll
        for (int mt = 0; mt < 4; mt++)
            #pragma unroll
            for (int nt = 0; nt < 4; nt++) {
                int m = m0 + wm + mt * 16 + q;
                int n = n0 + wn + nt * 8 + (lane & 3) * 2;
                float b0 = __ldg(&bias[n]), b1 = __ldg(&bias[n + 1]);
                *(float2*)&C[(size_t)m * 512 + n]       = make_float2(acc[mt][nt][0] + b0, acc[mt][nt][1] + b1);
                *(float2*)&C[(size_t)(m + 8) * 512 + n] = make_float2(acc[mt][nt][2] + b0, acc[mt][nt][3] + b1);
            }
    } else {
        __half* Ch = args.Ch[z];
        const bool do_exp = (mode == 1);
        #pragma unroll
        for (int mt = 0; mt < 4; mt++)
            #pragma unroll
            for (int nt = 0; nt < 4; nt++) {
                int m = m0 + wm + mt * 16 + q;
                int n = n0 + wn + nt * 8 + (lane & 3) * 2;
                float b0 = __ldg(&bias[n]), b1 = __ldg(&bias[n + 1]);
                float v0 = acc[mt][nt][0] + b0;
                float v1 = acc[mt][nt][1] + b1;
                float v2 = acc[mt][nt][2] + b0;
                float v3 = acc[mt][nt][3] + b1;
                if (do_exp) { v0 = __expf(v0); v1 = __expf(v1); v2 = __expf(v2); v3 = __expf(v3); }
                *(__half2*)&Ch[(size_t)m * 512 + n]       = __floats2half2_rn(v0, v1);
                *(__half2*)&Ch[(size_t)(m + 8) * 512 + n] = __floats2half2_rn(v2, v3);
            }
    }
}

// ================================================================================
// K2: per-(b,h,split) context partials via fp16 mma + ldmatrix.trans.
// Two-stage double-buffer (37 KB smem).  [R11 config]
// ================================================================================
#define CPT_H (64 * 72)
#define CPT_B ((uint32_t)CPT_H * 2)
#define CP_DSMEM (4 * CPT_H * 2 + 256)

__global__ void __launch_bounds__(128)
ctx_partial_kernel() {
    extern __shared__ __half smh[];
    const int sp = blockIdx.x, h = blockIdx.y, b = blockIdx.z;
    const int tid = threadIdx.x, warp = tid >> 5, lane = tid & 31;
    const int q = lane >> 2, r = lane & 3;
    const int rowbase = b * SEQ + sp * CHUNK;
    const int coloff = h * 64;
    const uint32_t sbase = smem_to_u32(smh);

    float acc[32];
    #pragma unroll
    for (int i = 0; i < 32; i++) acc[i] = 0.f;
    float ssum = 0.f;
    const int sd = tid & 63;
    const int sr0 = (tid >> 6) * 32;

    const int srow = tid >> 3;
    const int sc8  = (tid & 7) * 8;
    const uint32_t sOff = (uint32_t)(srow * 72 + sc8) * 2;

    const int lg = lane >> 3;
    const int lrowA = (lg >> 1) * 8 + (lane & 7);
    const int lcolA = warp * 16 + (lg & 1) * 8;
    const int lrowB = (lg & 1) * 8 + (lane & 7);
    const int lcolB0 = (lg >> 1) * 8;

    #pragma unroll
    for (int i = 0; i < 4; i++) {
        int row = srow + i * 16;
        uint32_t so = sOff + (uint32_t)i * 16 * 72 * 2;
        cp_async16(sbase + so,         &g_Eh[(size_t)(rowbase + row) * 512 + coloff + sc8]);
        cp_async16(sbase + CPT_B + so, &g_Vh[(size_t)(rowbase + row) * 512 + coloff + sc8]);
    }
    CP_COMMIT();

    #pragma unroll 1
    for (int g = 0; g < 4; g++) {
        __syncthreads();
        if (g + 1 < 4) {
            uint32_t bb = sbase + (uint32_t)((g + 1) & 1) * 2 * CPT_B;
            const int gr = rowbase + (g + 1) * 64;
            #pragma unroll
            for (int i = 0; i < 4; i++) {
                int row = srow + i * 16;
                uint32_t so = sOff + (uint32_t)i * 16 * 72 * 2;
                cp_async16(bb + so,         &g_Eh[(size_t)(gr + row) * 512 + coloff + sc8]);
                cp_async16(bb + CPT_B + so, &g_Vh[(size_t)(gr + row) * 512 + coloff + sc8]);
            }
        }
        CP_COMMIT();
        CP_WAIT1();
        __syncthreads();

        const uint32_t Eb = sbase + (uint32_t)(g & 1) * 2 * CPT_B;
        const uint32_t Vb = Eb + CPT_B;
        const __half* Es = (const __half*)(smh + (size_t)(g & 1) * 2 * CPT_H);

        #pragma unroll 8
        for (int n = 0; n < 32; n++) ssum += __half2float(Es[(sr0 + n) * 72 + sd]);

        #pragma unroll
        for (int kb = 0; kb < 4; kb++) {
            uint32_t af[4], bf[4][4];
            ldmx4t(af, Eb + (uint32_t)((kb * 16 + lrowA) * 72 + lcolA) * 2);
            #pragma unroll
            for (int eb = 0; eb < 4; eb++)
                ldmx4t(bf[eb], Vb + (uint32_t)((kb * 16 + lrowB) * 72 + eb * 16 + lcolB0) * 2);
            #pragma unroll
            for (int nt = 0; nt < 8; nt++) {
                int eb = nt >> 1, o = (nt & 1) * 2;
                mma_f16(acc[nt * 4 + 0], acc[nt * 4 + 1], acc[nt * 4 + 2], acc[nt * 4 + 3],
                        af[0], af[1], af[2], af[3],
                        bf[eb][o], bf[eb][o + 1]);
            }
        }
    }

    float* P = g_part + ((size_t)((b * NHEAD + h) * NSPLIT + sp)) * DK * 66;
    #pragma unroll
    for (int nt = 0; nt < 8; nt++) {
        int e = nt * 8 + r * 2;
        *(float2*)&P[(warp * 16 + q) * 66 + e]     = make_float2(acc[nt * 4 + 0], acc[nt * 4 + 1]);
        *(float2*)&P[(warp * 16 + q + 8) * 66 + e] = make_float2(acc[nt * 4 + 2], acc[nt * 4 + 3]);
    }
    float* ssc = (float*)(smh + 4 * CPT_H);
    if (tid >= 64) ssc[tid - 64] = ssum;
    __syncthreads();
    if (tid < 64) P[tid * 66 + 64] = ssum + ssc[tid];
}

// ================================================================================
// K3: reduce partials over splits, normalize -> g_ctx. grid (16 bh, 8 d-slabs).
// ================================================================================
__global__ void __launch_bounds__(256)
ctx_reduce_kernel() {
    const int bh = blockIdx.x, y = blockIdx.y;
    const int tid = threadIdx.x;
    __shared__ float s[528];
    const float* P = g_part + (size_t)bh * NSPLIT * 4224 + y * 8 * 66;
    for (int idx = tid; idx < 528; idx += 256) {
        float a0 = 0.f, a1 = 0.f, a2 = 0.f, a3 = 0.f;
        for (int sp = 0; sp < 64; sp += 4) {
            a0 += P[(size_t)(sp + 0) * 4224 + idx];
            a1 += P[(size_t)(sp + 1) * 4224 + idx];
            a2 += P[(size_t)(sp + 2) * 4224 + idx];
            a3 += P[(size_t)(sp + 3) * 4224 + idx];
        }
        s[idx] = (a0 + a1) + (a2 + a3);
    }
    __syncthreads();
    for (int i = tid; i < 512; i += 256) {
        int d = i >> 6, e = i & 63;
        g_ctx[(size_t)bh * 4096 + (y * 8 + d) * 64 + e] = s[d * 66 + e] / s[d * 66 + 64];
    }
}

// ================================================================================
// K3b: merged matrix M_b = ctx_b @ Wo, k-major, fp16 out
// ================================================================================
__global__ void __launch_bounds__(256)
ctx_mm_kernel() {
    const int bh = blockIdx.x;
    const int b = bh >> 3, h = bh & 7;
    const int tid = threadIdx.x;
    __shared__ float cs[64 * 65];

    for (int idx = tid; idx < 4096; idx += 256) {
        int d = idx >> 6, e = idx & 63;
        cs[e * 65 + d] = g_ctx[(size_t)bh * 4096 + idx];
    }
    __syncthreads();

    const int d = tid & 63;
    const int g = tid >> 6;
    const int nf0 = blockIdx.y * 128 + g * 32;
    __half* Mb = g_Mh + (size_t)b * D_MODEL * D_MODEL;

    for (int nfb = nf0; nfb < nf0 + 32; nfb += 8) {
        float a8[8];
        #pragma unroll
        for (int i = 0; i < 8; i++) a8[i] = 0.f;
        #pragma unroll 4
        for (int e0 = 0; e0 < 64; e0 += 4) {
            float c0 = cs[(e0 + 0) * 65 + d];
            float c1 = cs[(e0 + 1) * 65 + d];
            float c2 = cs[(e0 + 2) * 65 + d];
            float c3 = cs[(e0 + 3) * 65 + d];
            #pragma unroll
            for (int i = 0; i < 8; i++) {
                float4 w = *(const float4*)&g_Wo32[(size_t)(nfb + i) * 512 + h * 64 + e0];
                a8[i] += w.x * c0 + w.y * c1 + w.z * c2 + w.w * c3;
            }
        }
        #pragma unroll
        for (int i = 0; i < 8; i++)
            Mb[(size_t)(nfb + i) * 512 + h * 64 + d] = __float2half_rn(a8[i]);
    }
}

// ================================================================================
// launch
// ================================================================================
extern "C" void kernel_launch(void* const* d_in, const int* in_sizes, int n_in,
                              void* d_out, int out_size) {
    const float* q  = (const float*)d_in[0];
    const float* k  = (const float*)d_in[1];
    const float* v  = (const float*)d_in[2];
    const float* Wq = (const float*)d_in[3];
    const float* bq = (const float*)d_in[4];
    const float* Wk = (const float*)d_in[5];
    const float* bk = (const float*)d_in[6];
    const float* Wv = (const float*)d_in[7];
    const float* bv = (const float*)d_in[8];
    const float* Wo = (const float*)d_in[9];
    const float* bo = (const float*)d_in[10];

    __half *pQh, *pEh, *pVh, *pWh, *pMh;
    cudaGetSymbolAddress((void**)&pQh, g_Qh);
    cudaGetSymbolAddress((void**)&pEh, g_Eh);
    cudaGetSymbolAddress((void**)&pVh, g_Vh);
    cudaGetSymbolAddress((void**)&pWh, g_Wh);
    cudaGetSymbolAddress((void**)&pMh, g_Mh);

    cudaFuncSetAttribute(gemm_h<true>,  cudaFuncAttributeMaxDynamicSharedMemorySize, GT_DSMEM);
    cudaFuncSetAttribute(gemm_h<false>, cudaFuncAttributeMaxDynamicSharedMemorySize, GT_DSMEM);
    cudaFuncSetAttribute(ctx_partial_kernel, cudaFuncAttributeMaxDynamicSharedMemorySize, CP_DSMEM);

    transpose_w<<<dim3(16, 16, 4), 256>>>(Wq, Wk, Wv, Wo);            // #1
    noop_kernel<<<1, 32>>>();                                         // #2
    noop_kernel<<<1, 32>>>();                                         // #3

    // projections (fp32 A fused conversion): z0=Q(softmax fp16), z1=K(exp fp16), z2=V(plain fp16)
    GemmArgs pa;
    pa.A[0] = nullptr; pa.A[1] = nullptr; pa.A[2] = nullptr;
    pa.Af[0] = q; pa.Af[1] = k; pa.Af[2] = v;
    pa.W[0] = pWh + (size_t)0 * 262144; pa.W[1] = pWh + (size_t)1 * 262144; pa.W[2] = pWh + (size_t)2 * 262144;
    pa.bias[0] = bq; pa.bias[1] = bk; pa.bias[2] = bv;
    pa.C[0] = nullptr; pa.C[1] = nullptr; pa.C[2] = nullptr;
    pa.Ch[0] = pQh; pa.Ch[1] = pEh; pa.Ch[2] = pVh;
    pa.mode[0] = 2; pa.mode[1] = 1; pa.mode[2] = 3;
    pa.batchW = 0;
    gemm_h<true><<<dim3(MTOT / 128, 4, 3), 256, GT_DSMEM>>>(pa);      // #4 -> ncu

    ctx_partial_kernel<<<dim3(NSPLIT, NHEAD, BATCH), 128, CP_DSMEM>>>();
    ctx_reduce_kernel<<<dim3(BATCH * NHEAD, 8), 256>>>();
    ctx_mm_kernel<<<dim3(BATCH * NHEAD, 4), 256>>>();

    // output: out = Qf @ M_b + bo (fp16 A path, fp32 out)
    GemmArgs oa;
    oa.A[0] = pQh; oa.A[1] = pQh; oa.A[2] = pQh;
    oa.Af[0] = nullptr; oa.Af[1] = nullptr; oa.Af[2] = nullptr;
    oa.W[0] = pMh; oa.W[1] = pMh; oa.W[2] = pMh;
    oa.bias[0] = bo; oa.bias[1] = bo; oa.bias[2] = bo;
    oa.C[0] = (float*)d_out; oa.C[1] = oa.C[0]; oa.C[2] = oa.C[0];
    oa.Ch[0] = nullptr; oa.Ch[1] = nullptr; oa.Ch[2] = nullptr;
    oa.mode[0] = 0; oa.mode[1] = 0; oa.mode[2] = 0;
    oa.batchW = 1;
    gemm_h<false><<<dim3(MTOT / 128, 4, 1), 256, GT_DSMEM>>>(oa);
}